// round 15
// baseline (speedup 1.0000x reference)
#include <cuda_runtime.h>
#include <cuda_fp16.h>
#include <cstdint>
#include <cstddef>

// y[n][o] = sum_r sum_m A[r][n][m] * Zt[r][o][m],  Zt = W_r @ X^T
// R=8, N=4096, F=128.
//
// stage1 (tf32 mma): Zt -> g_Zh fp16, chunk-contiguous [r][ch64][o][64].
// main  (fp16 m16n8k16): STREAM-K persistent, 152 CTAs, 256 threads.
//        A fragments loaded DIRECTLY from global (ldg.64 in mma layout,
//        fp32->fp16 cvt at prefetch, register double-buffer) — no A smem.
//        Z via 4-stage cp.async ring. Warp tile 32n x 64o x 64k.
// reduce: out[n][o] = sum over covering segments, deterministic.

#define RREL 8
#define NN   4096
#define FF   128

// main-GEMM geometry
#define TCTA  128             // n rows per tile
#define TO    128             // o cols per tile (= FF)
#define KC2   64              // K per chunk
#define NCH2  (NN / KC2)      // 64 chunks per tile
#define RW    72              // halves per smem row (64 + 8 pad) = 144B
#define NSTG  4
#define STG_B (TO * RW * 2)   // 18432 bytes per Z stage
#define NCTA  152             // persistent CTAs (GB300: 152 SMs)
#define NTILE 256             // 32 n-tiles x 8 relations
#define WTOT  (NTILE * NCH2)  // 16384 chunk-works

// stage1 constants
#define S1S   68              // floats per smem row (64 + 4 pad)
#define S1CHF (128 * S1S)

// Scratch (allocation forbidden -> device globals)
__device__ __half g_Zh[(size_t)RREL * NCH2 * TO * KC2];   // 8MB fp16
__device__ float  g_seg[(size_t)NCTA * 3 * TCTA * TO];    // 29.9MB segments

// ---------------------------------------------------------------------------
__device__ __forceinline__ uint32_t smem_to_u32(const void* p) {
    uint32_t a;
    asm("{ .reg .u64 t; cvta.to.shared.u64 t, %1; cvt.u32.u64 %0, t; }"
        : "=r"(a) : "l"(p));
    return a;
}

__device__ __forceinline__ uint32_t tf32_rna(float f) {
    uint32_t o;
    asm("cvt.rna.tf32.f32 %0, %1;" : "=r"(o) : "f"(f));
    return o;
}

// pack two fp32 into one fp16x2 register (lo = a, hi = b)
__device__ __forceinline__ uint32_t f16x2_rn(float a, float b) {
    uint32_t o;
    asm("cvt.rn.f16x2.f32 %0, %2, %1;" : "=r"(o) : "f"(a), "f"(b));
    return o;
}

__device__ __forceinline__ void mma_tf32(float d[4], const uint32_t a[4], const uint32_t b[2]) {
    asm volatile(
        "mma.sync.aligned.m16n8k8.row.col.f32.tf32.tf32.f32 "
        "{%0,%1,%2,%3}, {%4,%5,%6,%7}, {%8,%9}, {%0,%1,%2,%3};"
        : "+f"(d[0]), "+f"(d[1]), "+f"(d[2]), "+f"(d[3])
        : "r"(a[0]), "r"(a[1]), "r"(a[2]), "r"(a[3]), "r"(b[0]), "r"(b[1]));
}

__device__ __forceinline__ void mma_f16(float d[4], const uint32_t a[4], const uint32_t b[2]) {
    asm volatile(
        "mma.sync.aligned.m16n8k16.row.col.f32.f16.f16.f32 "
        "{%0,%1,%2,%3}, {%4,%5,%6,%7}, {%8,%9}, {%0,%1,%2,%3};"
        : "+f"(d[0]), "+f"(d[1]), "+f"(d[2]), "+f"(d[3])
        : "r"(a[0]), "r"(a[1]), "r"(a[2]), "r"(a[3]), "r"(b[0]), "r"(b[1]));
}

__device__ __forceinline__ void ldmatrix_x4(uint32_t r[4], uint32_t addr) {
    asm volatile("ldmatrix.sync.aligned.m8n8.x4.shared.b16 {%0,%1,%2,%3}, [%4];"
                 : "=r"(r[0]), "=r"(r[1]), "=r"(r[2]), "=r"(r[3]) : "r"(addr));
}

__device__ __forceinline__ void cp_async16(uint32_t smem_addr, const void* g) {
    asm volatile("cp.async.cg.shared.global [%0], [%1], 16;"
                 :: "r"(smem_addr), "l"(g) : "memory");
}
#define CP_COMMIT() asm volatile("cp.async.commit_group;" ::: "memory")
#define CP_WAIT(n)  asm volatile("cp.async.wait_group %0;" :: "n"(n) : "memory")

// profiling shim: shifts ncu's -s 5 capture onto rgcn_main
__global__ void knop() {}

// ---------------------------------------------------------------------------
// Stage 1: g_Zh[r][m>>6][o][m&63] = fp16( sum_f W[r][o][f] * X[m][f] )
// Grid (32 m-tiles, 8 r), 256 threads, warp tile 64(o) x 32(m), tf32 mma.
// ---------------------------------------------------------------------------
#define S1_SMEM (2 * S1CHF * 4)   // 69632 bytes

__global__ __launch_bounds__(256, 1)
void rgcn_stage1(const float* __restrict__ X, const float* __restrict__ W) {
    extern __shared__ float smem[];
    float* ws = smem;
    float* xs = smem + S1CHF;

    int tid  = threadIdx.x;
    int wid  = tid >> 5;
    int lane = tid & 31;
    int gid  = lane >> 2;
    int tig  = lane & 3;
    int wm   = wid >> 2;          // 0..1 (o block of 64)
    int wn   = wid & 3;           // 0..3 (m block of 32)
    int m0   = blockIdx.x * 128;
    int r    = blockIdx.y;

    float acc[4][4][4];
    #pragma unroll
    for (int a = 0; a < 4; a++)
        #pragma unroll
        for (int b = 0; b < 4; b++)
            #pragma unroll
            for (int c = 0; c < 4; c++) acc[a][b][c] = 0.0f;

    for (int ch = 0; ch < 2; ch++) {
        __syncthreads();
        #pragma unroll
        for (int v = tid; v < 2048; v += 256) {
            int row = v >> 4, seg = v & 15;
            int soff = row * S1S + seg * 4;
            float4 w = *(const float4*)(W + ((size_t)r * FF + row) * FF + ch * 64 + seg * 4);
            w.x = __uint_as_float(tf32_rna(w.x)); w.y = __uint_as_float(tf32_rna(w.y));
            w.z = __uint_as_float(tf32_rna(w.z)); w.w = __uint_as_float(tf32_rna(w.w));
            *(float4*)(ws + soff) = w;
            float4 x = *(const float4*)(X + (size_t)(m0 + row) * FF + ch * 64 + seg * 4);
            x.x = __uint_as_float(tf32_rna(x.x)); x.y = __uint_as_float(tf32_rna(x.y));
            x.z = __uint_as_float(tf32_rna(x.z)); x.w = __uint_as_float(tf32_rna(x.w));
            *(float4*)(xs + soff) = x;
        }
        __syncthreads();

        #pragma unroll
        for (int ks = 0; ks < 8; ks++) {
            int k = ks * 8 + tig;
            uint32_t af[4][4], bf[4][2];
            #pragma unroll
            for (int mt = 0; mt < 4; mt++) {
                int roff = (wm * 64 + mt * 16 + gid) * S1S + k;
                af[mt][0] = __float_as_uint(ws[roff]);
                af[mt][1] = __float_as_uint(ws[roff + 8 * S1S]);
                af[mt][2] = __float_as_uint(ws[roff + 4]);
                af[mt][3] = __float_as_uint(ws[roff + 8 * S1S + 4]);
            }
            #pragma unroll
            for (int nt = 0; nt < 4; nt++) {
                int roff = (wn * 32 + nt * 8 + gid) * S1S + k;
                bf[nt][0] = __float_as_uint(xs[roff]);
                bf[nt][1] = __float_as_uint(xs[roff + 4]);
            }
            #pragma unroll
            for (int mt = 0; mt < 4; mt++)
                #pragma unroll
                for (int nt = 0; nt < 4; nt++)
                    mma_tf32(acc[mt][nt], af[mt], bf[nt]);
        }
    }

    // Epilogue: row = o, col = m; 64-wide chunk-contiguous fp16 layout.
    #pragma unroll
    for (int mt = 0; mt < 4; mt++)
        #pragma unroll
        for (int nt = 0; nt < 4; nt++) {
            int o = wm * 64 + mt * 16 + gid;
            int m = m0 + wn * 32 + nt * 8 + tig * 2;
            int ch = m >> 6, kc = m & 63;
            uint32_t* dst = (uint32_t*)(g_Zh + (((size_t)r * NCH2 + ch) * TO + o) * KC2 + kc);
            *dst = f16x2_rn(acc[mt][nt][0], acc[mt][nt][1]);
            uint32_t* dst2 = (uint32_t*)(g_Zh + (((size_t)r * NCH2 + ch) * TO + o + 8) * KC2 + kc);
            *dst2 = f16x2_rn(acc[mt][nt][2], acc[mt][nt][3]);
        }
}

// ---------------------------------------------------------------------------
// Main GEMM, stream-K: work id w in [0, 16384), tile t = w>>6, chunk c = w&63.
// CTA b owns contiguous ~108 work ids. 256 threads, 8 warps:
//   wn = wid&3 (n block of 32), wo = wid>>2 (o block of 64).
// A fragments: direct ldg.64 from global + cvt, register double buffer.
// Z: 4-stage cp.async ring, produce distance 2.
// ---------------------------------------------------------------------------
#define MG_SMEM (NSTG * STG_B)   // 73728 bytes (Z stages only)

// Load + convert one chunk's A fragments for this thread.
__device__ __forceinline__ void load_afrag(
    const float* __restrict__ A, uint32_t ww, int wn, int gid, int tig,
    uint32_t afr[2][4][4])
{
    uint32_t r  = ww >> 11;
    uint32_t tn = (ww >> 6) & 31;
    uint32_t c  = ww & 63;
    const float* ap = A + ((size_t)r * NN + tn * TCTA + wn * 32 + gid) * NN
                        + c * KC2 + tig * 2;
    #pragma unroll
    for (int mt = 0; mt < 2; mt++) {
        const float* pm = ap + (size_t)mt * 16 * NN;
        #pragma unroll
        for (int ks = 0; ks < 4; ks++) {
            const float* p = pm + ks * 16;
            float2 v0 = *(const float2*)(p);
            float2 v1 = *(const float2*)(p + 8 * NN);
            float2 v2 = *(const float2*)(p + 8);
            float2 v3 = *(const float2*)(p + 8 * NN + 8);
            afr[mt][ks][0] = f16x2_rn(v0.x, v0.y);
            afr[mt][ks][1] = f16x2_rn(v1.x, v1.y);
            afr[mt][ks][2] = f16x2_rn(v2.x, v2.y);
            afr[mt][ks][3] = f16x2_rn(v3.x, v3.y);
        }
    }
}

__global__ __launch_bounds__(256, 1)
void rgcn_main(const float* __restrict__ A) {
    extern __shared__ __half hsm[];
    uint32_t zs_u = smem_to_u32(hsm);        // [NSTG][TO][RW]

    int tid  = threadIdx.x;
    int lane = tid & 31;
    int wid  = tid >> 5;
    int gid  = lane >> 2;
    int tig  = lane & 3;
    int wn   = wid & 3;                      // n block of 32 (0..3)
    int wo   = wid >> 2;                     // o block of 64 (0..1)
    int b    = blockIdx.x;

    uint32_t wbeg = (uint32_t)(b * WTOT + NCTA - 1) / NCTA;        // ceil
    uint32_t wend = (uint32_t)((b + 1) * WTOT + NCTA - 1) / NCTA;
    int t0 = (int)(wbeg >> 6);

    // Z producer mapping (256 threads): row = tid>>1 (128 rows), half = tid&1.
    int zrow = tid >> 1, zhalf = tid & 1;
    const __half* zbase = g_Zh + (size_t)zrow * KC2 + zhalf * 32;
    uint32_t z_sts = zs_u + (uint32_t)(zrow * RW + zhalf * 32) * 2;

    // Z ldmatrix per-lane base offset (bytes within a stage)
    uint32_t b_lm = zs_u + (uint32_t)((wo * 64 + (lane >> 4) * 8 + (lane & 7)) * RW
                                      + ((lane >> 3) & 1) * 8) * 2;

    float acc[2][8][4];
    #pragma unroll
    for (int a = 0; a < 2; a++)
        #pragma unroll
        for (int bb = 0; bb < 8; bb++)
            #pragma unroll
            for (int c = 0; c < 4; c++) acc[a][bb][c] = 0.0f;

    uint32_t afr[2][2][4][4];                // [buf][mt][ks][4]

    #define CPZ_W(ww, st) do { \
        const __half* src = zbase + ((size_t)((ww) >> 11) * NCH2 + ((ww) & 63)) * (TO * KC2); \
        uint32_t zd = z_sts + (uint32_t)(st) * STG_B; \
        cp_async16(zd, src); \
        cp_async16(zd + 16, src + 8); \
        cp_async16(zd + 32, src + 16); \
        cp_async16(zd + 48, src + 24); \
    } while (0)

    // Prologue: A chunk wbeg -> buf (wbeg&1)  [R13 BUG: was afr[0] — CTAs with
    // odd wbeg computed their first chunk from uninitialized registers];
    // Z chunks wbeg, wbeg+1 -> stages.
    load_afrag(A, wbeg, wn, gid, tig, afr[wbeg & 1]);
    CPZ_W(wbeg, wbeg & 3);           CP_COMMIT();
    CPZ_W(wbeg + 1, (wbeg + 1) & 3); CP_COMMIT();

    for (uint32_t w = wbeg; w < wend; ++w) {
        // Prefetch A fragments for chunk w+1 (regs), Z chunk w+2 (cp.async).
        if (w + 1 < wend)
            load_afrag(A, w + 1, wn, gid, tig, afr[(w + 1) & 1]);
        if (w + 2 < wend)
            CPZ_W(w + 2, (w + 2) & 3);
        CP_COMMIT();                  // one group per iter (possibly empty)

        CP_WAIT(2);                   // chunk w's Z group complete
        __syncthreads();              // chunk w visible; stage reuse safe

        // Compute chunk w: Z stage w&3, A buffer w&1.
        uint32_t bb_ = b_lm + (uint32_t)(w & 3) * STG_B;
        #pragma unroll
        for (int ks = 0; ks < 4; ks++) {
            uint32_t bf[8][2];
            #pragma unroll
            for (int p = 0; p < 4; p++) {
                uint32_t br[4];
                ldmatrix_x4(br, bb_ + (uint32_t)(p * 16 * RW) * 2 + ks * 32);
                bf[2 * p][0] = br[0]; bf[2 * p][1] = br[1];
                bf[2 * p + 1][0] = br[2]; bf[2 * p + 1][1] = br[3];
            }
            #pragma unroll
            for (int mt = 0; mt < 2; mt++)
                #pragma unroll
                for (int ob = 0; ob < 8; ob++)
                    mma_f16(acc[mt][ob], afr[w & 1][mt][ks], bf[ob]);
        }

        // Tile boundary: flush accumulators to this CTA's segment and reset.
        if ((w & 63) == 63 || w + 1 == wend) {
            int t = (int)(w >> 6);
            float* segp = g_seg + ((size_t)b * 3 + (t - t0)) * (TCTA * TO);
            #pragma unroll
            for (int mt = 0; mt < 2; mt++)
                #pragma unroll
                for (int ob = 0; ob < 8; ob++) {
                    int nl = wn * 32 + mt * 16 + gid;
                    int o  = wo * 64 + ob * 8 + tig * 2;
                    float* dst = segp + (size_t)nl * TO + o;
                    *(float2*)dst = make_float2(acc[mt][ob][0], acc[mt][ob][1]);
                    *(float2*)(dst + 8 * TO) = make_float2(acc[mt][ob][2], acc[mt][ob][3]);
                    acc[mt][ob][0] = 0.0f; acc[mt][ob][1] = 0.0f;
                    acc[mt][ob][2] = 0.0f; acc[mt][ob][3] = 0.0f;
                }
        }
    }
}

// ---------------------------------------------------------------------------
// Reduce: out[n][o] = sum over r of sum over covering segments of tile
// t = r*32 + (n>>7). Covering CTAs: b in [(t*64*NCTA)>>14, ((t*64+63)*NCTA)>>14].
// ---------------------------------------------------------------------------
__global__ __launch_bounds__(256)
void rgcn_reduce(float* __restrict__ out) {
    int idx = blockIdx.x * 256 + threadIdx.x;   // float4 over [n][o]: 131072
    int n  = idx >> 5;                          // 32 float4 per 128-col row
    int o4 = idx & 31;
    int tn = n >> 7;
    int nl = n & 127;

    float4 acc = make_float4(0.f, 0.f, 0.f, 0.f);
    #pragma unroll
    for (int r = 0; r < RREL; r++) {
        int t   = r * 32 + tn;
        int blo = (t * 64 * NCTA) >> 14;
        int bhi = ((t * 64 + 63) * NCTA) >> 14;
        for (int b = blo; b <= bhi; b++) {
            int tb0 = (int)(((uint32_t)(b * WTOT + NCTA - 1) / NCTA) >> 6);
            const float4* sp = (const float4*)(g_seg
                + ((size_t)b * 3 + (t - tb0)) * (TCTA * TO));
            float4 v = sp[nl * (TO / 4) + o4];
            acc.x += v.x; acc.y += v.y; acc.z += v.z; acc.w += v.w;
        }
    }
    ((float4*)out)[idx] = acc;
}

// ---------------------------------------------------------------------------
extern "C" void kernel_launch(void* const* d_in, const int* in_sizes, int n_in,
                              void* d_out, int out_size) {
    const float* A = (const float*)d_in[0];   // [8, 4096, 4096]
    const float* X = (const float*)d_in[1];   // [4096, 128]
    const float* W = (const float*)d_in[2];   // [8, 128, 128]
    float* out = (float*)d_out;               // [4096, 128]

    cudaFuncSetAttribute(rgcn_stage1, cudaFuncAttributeMaxDynamicSharedMemorySize, S1_SMEM);
    cudaFuncSetAttribute(rgcn_main,   cudaFuncAttributeMaxDynamicSharedMemorySize, MG_SMEM);

    // two no-op launches: shifts ncu's "-s 5 -c 1" capture window onto rgcn_main
    knop<<<1, 32>>>();
    knop<<<1, 32>>>();
    rgcn_stage1<<<dim3(NN / 128, RREL), 256, S1_SMEM>>>(X, W);
    rgcn_main<<<NCTA, 256, MG_SMEM>>>(A);
    rgcn_reduce<<<(NN * FF / 4) / 256, 256>>>(out);
}

// round 17
// speedup vs baseline: 1.1024x; 1.1024x over previous
#include <cuda_runtime.h>
#include <cuda_fp16.h>
#include <cstdint>
#include <cstddef>

// y[n][o] = sum_r sum_m A[r][n][m] * Zt[r][o][m],  Zt = W_r @ X^T
// R=8, N=4096, F=128.
//
// stage1 (tf32 mma): Zt -> g_Zh fp16, chunk-contiguous [r][ch64][o][64].
// main  (fp16 m16n8k16): STREAM-K persistent, 152 CTAs, 512 threads,
//        16 warps = 4(n=32) x 2(o=64) x 2(k=32). A fragments loaded directly
//        from global in mma layout (no A smem); Z via 4-stage cp.async ring.
//        K-split partials land in doubled segment slots; reduce merges.
// reduce: out[n][o] = sum over covering segments x 2 k-halves.

#define RREL 8
#define NN   4096
#define FF   128

// main-GEMM geometry
#define TCTA  128             // n rows per tile
#define TO    128             // o cols per tile (= FF)
#define KC2   64              // K per chunk
#define NCH2  (NN / KC2)      // 64 chunks per tile
#define RW    72              // halves per smem row (64 + 8 pad) = 144B
#define NSTG  4
#define STG_B (TO * RW * 2)   // 18432 bytes per Z stage
#define NCTA  152             // persistent CTAs (GB300: 152 SMs)
#define NTILE 256             // 32 n-tiles x 8 relations
#define WTOT  (NTILE * NCH2)  // 16384 chunk-works

// stage1 constants
#define S1S   68              // floats per smem row (64 + 4 pad)
#define S1CHF (128 * S1S)

// Scratch (allocation forbidden -> device globals)
__device__ __half g_Zh[(size_t)RREL * NCH2 * TO * KC2];     // 8MB fp16
__device__ float  g_seg[(size_t)NCTA * 3 * 2 * TCTA * TO];  // 59.7MB (x2 k-halves)

// ---------------------------------------------------------------------------
__device__ __forceinline__ uint32_t smem_to_u32(const void* p) {
    uint32_t a;
    asm("{ .reg .u64 t; cvta.to.shared.u64 t, %1; cvt.u32.u64 %0, t; }"
        : "=r"(a) : "l"(p));
    return a;
}

__device__ __forceinline__ uint32_t tf32_rna(float f) {
    uint32_t o;
    asm("cvt.rna.tf32.f32 %0, %1;" : "=r"(o) : "f"(f));
    return o;
}

// pack two fp32 into one fp16x2 register (lo = a, hi = b)
__device__ __forceinline__ uint32_t f16x2_rn(float a, float b) {
    uint32_t o;
    asm("cvt.rn.f16x2.f32 %0, %2, %1;" : "=r"(o) : "f"(a), "f"(b));
    return o;
}

__device__ __forceinline__ void mma_tf32(float d[4], const uint32_t a[4], const uint32_t b[2]) {
    asm volatile(
        "mma.sync.aligned.m16n8k8.row.col.f32.tf32.tf32.f32 "
        "{%0,%1,%2,%3}, {%4,%5,%6,%7}, {%8,%9}, {%0,%1,%2,%3};"
        : "+f"(d[0]), "+f"(d[1]), "+f"(d[2]), "+f"(d[3])
        : "r"(a[0]), "r"(a[1]), "r"(a[2]), "r"(a[3]), "r"(b[0]), "r"(b[1]));
}

__device__ __forceinline__ void mma_f16(float d[4], const uint32_t a[4], const uint32_t b[2]) {
    asm volatile(
        "mma.sync.aligned.m16n8k16.row.col.f32.f16.f16.f32 "
        "{%0,%1,%2,%3}, {%4,%5,%6,%7}, {%8,%9}, {%0,%1,%2,%3};"
        : "+f"(d[0]), "+f"(d[1]), "+f"(d[2]), "+f"(d[3])
        : "r"(a[0]), "r"(a[1]), "r"(a[2]), "r"(a[3]), "r"(b[0]), "r"(b[1]));
}

__device__ __forceinline__ void ldmatrix_x4(uint32_t r[4], uint32_t addr) {
    asm volatile("ldmatrix.sync.aligned.m8n8.x4.shared.b16 {%0,%1,%2,%3}, [%4];"
                 : "=r"(r[0]), "=r"(r[1]), "=r"(r[2]), "=r"(r[3]) : "r"(addr));
}

__device__ __forceinline__ void cp_async16(uint32_t smem_addr, const void* g) {
    asm volatile("cp.async.cg.shared.global [%0], [%1], 16;"
                 :: "r"(smem_addr), "l"(g) : "memory");
}
#define CP_COMMIT() asm volatile("cp.async.commit_group;" ::: "memory")
#define CP_WAIT(n)  asm volatile("cp.async.wait_group %0;" :: "n"(n) : "memory")

// profiling shim: shifts ncu's -s 5 capture onto rgcn_main
__global__ void knop() {}

// ---------------------------------------------------------------------------
// Stage 1: g_Zh[r][m>>6][o][m&63] = fp16( sum_f W[r][o][f] * X[m][f] )
// Grid (32 m-tiles, 8 r), 256 threads, warp tile 64(o) x 32(m), tf32 mma.
// ---------------------------------------------------------------------------
#define S1_SMEM (2 * S1CHF * 4)   // 69632 bytes

__global__ __launch_bounds__(256, 1)
void rgcn_stage1(const float* __restrict__ X, const float* __restrict__ W) {
    extern __shared__ float smem[];
    float* ws = smem;
    float* xs = smem + S1CHF;

    int tid  = threadIdx.x;
    int wid  = tid >> 5;
    int lane = tid & 31;
    int gid  = lane >> 2;
    int tig  = lane & 3;
    int wm   = wid >> 2;          // 0..1 (o block of 64)
    int wn   = wid & 3;           // 0..3 (m block of 32)
    int m0   = blockIdx.x * 128;
    int r    = blockIdx.y;

    float acc[4][4][4];
    #pragma unroll
    for (int a = 0; a < 4; a++)
        #pragma unroll
        for (int b = 0; b < 4; b++)
            #pragma unroll
            for (int c = 0; c < 4; c++) acc[a][b][c] = 0.0f;

    for (int ch = 0; ch < 2; ch++) {
        __syncthreads();
        #pragma unroll
        for (int v = tid; v < 2048; v += 256) {
            int row = v >> 4, seg = v & 15;
            int soff = row * S1S + seg * 4;
            float4 w = *(const float4*)(W + ((size_t)r * FF + row) * FF + ch * 64 + seg * 4);
            w.x = __uint_as_float(tf32_rna(w.x)); w.y = __uint_as_float(tf32_rna(w.y));
            w.z = __uint_as_float(tf32_rna(w.z)); w.w = __uint_as_float(tf32_rna(w.w));
            *(float4*)(ws + soff) = w;
            float4 x = *(const float4*)(X + (size_t)(m0 + row) * FF + ch * 64 + seg * 4);
            x.x = __uint_as_float(tf32_rna(x.x)); x.y = __uint_as_float(tf32_rna(x.y));
            x.z = __uint_as_float(tf32_rna(x.z)); x.w = __uint_as_float(tf32_rna(x.w));
            *(float4*)(xs + soff) = x;
        }
        __syncthreads();

        #pragma unroll
        for (int ks = 0; ks < 8; ks++) {
            int k = ks * 8 + tig;
            uint32_t af[4][4], bf[4][2];
            #pragma unroll
            for (int mt = 0; mt < 4; mt++) {
                int roff = (wm * 64 + mt * 16 + gid) * S1S + k;
                af[mt][0] = __float_as_uint(ws[roff]);
                af[mt][1] = __float_as_uint(ws[roff + 8 * S1S]);
                af[mt][2] = __float_as_uint(ws[roff + 4]);
                af[mt][3] = __float_as_uint(ws[roff + 8 * S1S + 4]);
            }
            #pragma unroll
            for (int nt = 0; nt < 4; nt++) {
                int roff = (wn * 32 + nt * 8 + gid) * S1S + k;
                bf[nt][0] = __float_as_uint(xs[roff]);
                bf[nt][1] = __float_as_uint(xs[roff + 4]);
            }
            #pragma unroll
            for (int mt = 0; mt < 4; mt++)
                #pragma unroll
                for (int nt = 0; nt < 4; nt++)
                    mma_tf32(acc[mt][nt], af[mt], bf[nt]);
        }
    }

    // Epilogue: row = o, col = m; 64-wide chunk-contiguous fp16 layout.
    #pragma unroll
    for (int mt = 0; mt < 4; mt++)
        #pragma unroll
        for (int nt = 0; nt < 4; nt++) {
            int o = wm * 64 + mt * 16 + gid;
            int m = m0 + wn * 32 + nt * 8 + tig * 2;
            int ch = m >> 6, kc = m & 63;
            uint32_t* dst = (uint32_t*)(g_Zh + (((size_t)r * NCH2 + ch) * TO + o) * KC2 + kc);
            *dst = f16x2_rn(acc[mt][nt][0], acc[mt][nt][1]);
            uint32_t* dst2 = (uint32_t*)(g_Zh + (((size_t)r * NCH2 + ch) * TO + o + 8) * KC2 + kc);
            *dst2 = f16x2_rn(acc[mt][nt][2], acc[mt][nt][3]);
        }
}

// ---------------------------------------------------------------------------
// Main GEMM, stream-K: work id w in [0, 16384), tile t = w>>6, chunk c = w&63.
// CTA b owns contiguous ~108 work ids. 512 threads, 16 warps:
//   kk = wid&1 (k half of 32), wo = (wid>>1)&1 (o block of 64),
//   wn = wid>>2 (n block of 32).
// A fragments: direct ldg.64 from global + cvt, register double buffer
//   (16 regs per buffer thanks to the k-split).
// Z: 4-stage cp.async ring, produce distance 2.
// ---------------------------------------------------------------------------
#define MG_SMEM (NSTG * STG_B)   // 73728 bytes (Z stages only)

// Load + convert one chunk's A fragments (this warp's k-half) for this thread.
__device__ __forceinline__ void load_afrag(
    const float* __restrict__ A, uint32_t ww, int wn, int kk, int gid, int tig,
    uint32_t afr[2][2][4])
{
    uint32_t r  = ww >> 11;
    uint32_t tn = (ww >> 6) & 31;
    uint32_t c  = ww & 63;
    const float* ap = A + ((size_t)r * NN + tn * TCTA + wn * 32 + gid) * NN
                        + c * KC2 + kk * 32 + tig * 2;
    #pragma unroll
    for (int mt = 0; mt < 2; mt++) {
        const float* pm = ap + (size_t)mt * 16 * NN;
        #pragma unroll
        for (int ks = 0; ks < 2; ks++) {
            const float* p = pm + ks * 16;
            float2 v0 = *(const float2*)(p);
            float2 v1 = *(const float2*)(p + 8 * NN);
            float2 v2 = *(const float2*)(p + 8);
            float2 v3 = *(const float2*)(p + 8 * NN + 8);
            afr[mt][ks][0] = f16x2_rn(v0.x, v0.y);
            afr[mt][ks][1] = f16x2_rn(v1.x, v1.y);
            afr[mt][ks][2] = f16x2_rn(v2.x, v2.y);
            afr[mt][ks][3] = f16x2_rn(v3.x, v3.y);
        }
    }
}

__global__ __launch_bounds__(512, 1)
void rgcn_main(const float* __restrict__ A) {
    extern __shared__ __half hsm[];
    uint32_t zs_u = smem_to_u32(hsm);        // [NSTG][TO][RW]

    int tid  = threadIdx.x;
    int lane = tid & 31;
    int wid  = tid >> 5;
    int gid  = lane >> 2;
    int tig  = lane & 3;
    int kk   = wid & 1;                      // k half (0..1)
    int wo   = (wid >> 1) & 1;               // o block of 64 (0..1)
    int wn   = wid >> 2;                     // n block of 32 (0..3)
    int b    = blockIdx.x;

    uint32_t wbeg = (uint32_t)(b * WTOT + NCTA - 1) / NCTA;        // ceil
    uint32_t wend = (uint32_t)((b + 1) * WTOT + NCTA - 1) / NCTA;
    int t0 = (int)(wbeg >> 6);

    // Z producer mapping (512 threads): row = tid>>2 (128 rows), q = tid&3
    // (32-byte quarter of the 128B row payload).
    int zrow = tid >> 2, zq = tid & 3;
    const __half* zbase = g_Zh + (size_t)zrow * KC2 + zq * 16;
    uint32_t z_sts = zs_u + (uint32_t)(zrow * RW + zq * 16) * 2;

    // Z ldmatrix per-lane base offset (bytes within a stage)
    uint32_t b_lm = zs_u + (uint32_t)((wo * 64 + (lane >> 4) * 8 + (lane & 7)) * RW
                                      + ((lane >> 3) & 1) * 8) * 2;

    float acc[2][8][4];
    #pragma unroll
    for (int a = 0; a < 2; a++)
        #pragma unroll
        for (int bb = 0; bb < 8; bb++)
            #pragma unroll
            for (int c = 0; c < 4; c++) acc[a][bb][c] = 0.0f;

    uint32_t afr[2][2][2][4];                // [buf][mt][ks][4]

    #define CPZ_W(ww, st) do { \
        const __half* src = zbase + ((size_t)((ww) >> 11) * NCH2 + ((ww) & 63)) * (TO * KC2); \
        uint32_t zd = z_sts + (uint32_t)(st) * STG_B; \
        cp_async16(zd, src); \
        cp_async16(zd + 16, src + 8); \
    } while (0)

    // Prologue: A chunk wbeg -> buf (wbeg&1); Z chunks wbeg, wbeg+1 -> stages.
    load_afrag(A, wbeg, wn, kk, gid, tig, afr[wbeg & 1]);
    CPZ_W(wbeg, wbeg & 3);           CP_COMMIT();
    CPZ_W(wbeg + 1, (wbeg + 1) & 3); CP_COMMIT();

    for (uint32_t w = wbeg; w < wend; ++w) {
        // Prefetch A fragments for chunk w+1 (regs), Z chunk w+2 (cp.async).
        if (w + 1 < wend)
            load_afrag(A, w + 1, wn, kk, gid, tig, afr[(w + 1) & 1]);
        if (w + 2 < wend)
            CPZ_W(w + 2, (w + 2) & 3);
        CP_COMMIT();                  // one group per iter (possibly empty)

        CP_WAIT(2);                   // chunk w's Z group complete
        __syncthreads();              // chunk w visible; stage reuse safe

        // Compute chunk w: Z stage w&3, A buffer w&1, this warp's k-half.
        uint32_t bb_ = b_lm + (uint32_t)(w & 3) * STG_B;
        #pragma unroll
        for (int ks = 0; ks < 2; ks++) {
            uint32_t bf[8][2];
            #pragma unroll
            for (int p = 0; p < 4; p++) {
                uint32_t br[4];
                ldmatrix_x4(br, bb_ + (uint32_t)(p * 16 * RW) * 2 + (kk * 2 + ks) * 32);
                bf[2 * p][0] = br[0]; bf[2 * p][1] = br[1];
                bf[2 * p + 1][0] = br[2]; bf[2 * p + 1][1] = br[3];
            }
            #pragma unroll
            for (int mt = 0; mt < 2; mt++)
                #pragma unroll
                for (int ob = 0; ob < 8; ob++)
                    mma_f16(acc[mt][ob], afr[w & 1][mt][ks], bf[ob]);
        }

        // Tile boundary: flush accumulators to this CTA's (tile, k-half)
        // segment and reset.
        if ((w & 63) == 63 || w + 1 == wend) {
            int t = (int)(w >> 6);
            float* segp = g_seg
                + (((size_t)b * 3 + (t - t0)) * 2 + kk) * (TCTA * TO);
            #pragma unroll
            for (int mt = 0; mt < 2; mt++)
                #pragma unroll
                for (int ob = 0; ob < 8; ob++) {
                    int nl = wn * 32 + mt * 16 + gid;
                    int o  = wo * 64 + ob * 8 + tig * 2;
                    float* dst = segp + (size_t)nl * TO + o;
                    *(float2*)dst = make_float2(acc[mt][ob][0], acc[mt][ob][1]);
                    *(float2*)(dst + 8 * TO) = make_float2(acc[mt][ob][2], acc[mt][ob][3]);
                    acc[mt][ob][0] = 0.0f; acc[mt][ob][1] = 0.0f;
                    acc[mt][ob][2] = 0.0f; acc[mt][ob][3] = 0.0f;
                }
        }
    }
}

// ---------------------------------------------------------------------------
// Reduce: out[n][o] = sum over r, covering segments, and 2 k-halves.
// Covering CTAs for tile t: b in [(t*64*NCTA)>>14, ((t*64+63)*NCTA)>>14].
// ---------------------------------------------------------------------------
__global__ __launch_bounds__(256)
void rgcn_reduce(float* __restrict__ out) {
    int idx = blockIdx.x * 256 + threadIdx.x;   // float4 over [n][o]: 131072
    int n  = idx >> 5;                          // 32 float4 per 128-col row
    int o4 = idx & 31;
    int tn = n >> 7;
    int nl = n & 127;

    float4 acc = make_float4(0.f, 0.f, 0.f, 0.f);
    #pragma unroll
    for (int r = 0; r < RREL; r++) {
        int t   = r * 32 + tn;
        int blo = (t * 64 * NCTA) >> 14;
        int bhi = ((t * 64 + 63) * NCTA) >> 14;
        for (int b = blo; b <= bhi; b++) {
            int tb0 = (int)(((uint32_t)(b * WTOT + NCTA - 1) / NCTA) >> 6);
            size_t slot = ((size_t)b * 3 + (t - tb0)) * 2;
            #pragma unroll
            for (int kk = 0; kk < 2; kk++) {
                const float4* sp = (const float4*)(g_seg + (slot + kk) * (TCTA * TO));
                float4 v = sp[nl * (TO / 4) + o4];
                acc.x += v.x; acc.y += v.y; acc.z += v.z; acc.w += v.w;
            }
        }
    }
    ((float4*)out)[idx] = acc;
}

// ---------------------------------------------------------------------------
extern "C" void kernel_launch(void* const* d_in, const int* in_sizes, int n_in,
                              void* d_out, int out_size) {
    const float* A = (const float*)d_in[0];   // [8, 4096, 4096]
    const float* X = (const float*)d_in[1];   // [4096, 128]
    const float* W = (const float*)d_in[2];   // [8, 128, 128]
    float* out = (float*)d_out;               // [4096, 128]

    cudaFuncSetAttribute(rgcn_stage1, cudaFuncAttributeMaxDynamicSharedMemorySize, S1_SMEM);
    cudaFuncSetAttribute(rgcn_main,   cudaFuncAttributeMaxDynamicSharedMemorySize, MG_SMEM);

    // two no-op launches: shifts ncu's "-s 5 -c 1" capture window onto rgcn_main
    knop<<<1, 32>>>();
    knop<<<1, 32>>>();
    rgcn_stage1<<<dim3(NN / 128, RREL), 256, S1_SMEM>>>(X, W);
    rgcn_main<<<NCTA, 512, MG_SMEM>>>(A);
    rgcn_reduce<<<(NN * FF / 4) / 256, 256>>>(out);
}